// round 16
// baseline (speedup 1.0000x reference)
#include <cuda_runtime.h>
#include <cuda_fp16.h>
#include <cstdint>

#define FULL 0xffffffffu
typedef unsigned long long ull;

__constant__ int UOFF[7] = {0, 11577, 11588, 11599, 11610, 11621, 11642};
__constant__ int VOFF[5] = {0, 4733, 4754, 4761, 4772};

constexpr int NWARP = 20;
constexpr int NTHREADS = NWARP * 32;         // 640
constexpr int XS_STRIDE = 9;
constexpr int XS_FLOATS = 128 * XS_STRIDE;   // 1152 per warp
constexpr int AW_WORDS = 32 * 32 * 4;        // 4096 words: fp16 A-frag table
constexpr int UP_FLOATS = (3 * 49 + 7) * 64; // 9856 fp32: user pair tables + single
constexpr int VP_FLOATS = (2 * 49 + 7) * 64; // 6720 fp32: url pair tables + single
constexpr int UP_ENT = 3 * 49 + 7;           // 154
constexpr int VP_ENT = 2 * 49 + 7;           // 105
constexpr int PAIR_F32_B = 49 * 256;
constexpr int PAIR_F16_B = 49 * 128;
constexpr int SMEM_WORDS = AW_WORDS + UP_FLOATS + VP_FLOATS
                         + UP_ENT * 32 + VP_ENT * 32 + NWARP * XS_FLOATS;
constexpr int SMEM_BYTES = SMEM_WORDS * 4;   // 208000

__device__ unsigned W1TH[128 * 32];  // half2(W1[l][i], W1[l+32][i]) at [i*32+l]
__device__ unsigned int g_ctr;

__global__ void prep_kernel(const float* __restrict__ W1) {
    int i = blockIdx.x * blockDim.x + threadIdx.x;
    if (i == 0) g_ctr = 0;
    if (i < 128 * 32) {
        int col = i >> 5, l = i & 31;
        __half2 h = __floats2half2_rn(W1[l * 128 + col], W1[(l + 32) * 128 + col]);
        W1TH[i] = *(unsigned*)&h;
    }
}

__device__ __forceinline__ float bfly_add(float v) {
#pragma unroll
    for (int o = 16; o; o >>= 1) v += __shfl_xor_sync(FULL, v, o);
    return v;
}
__device__ __forceinline__ void addp(ull& a, ull b) {
    asm("add.rn.f32x2 %0, %0, %1;" : "+l"(a) : "l"(b));
}
__device__ __forceinline__ ull pack2(float x, float y) {
    ull r; asm("mov.b64 %0, {%1, %2};" : "=l"(r) : "f"(x), "f"(y));
    return r;
}
__device__ __forceinline__ float lo32(ull v) { return __uint_as_float((unsigned)v); }
__device__ __forceinline__ float hi32(ull v) { return __uint_as_float((unsigned)(v >> 32)); }

__device__ __forceinline__ unsigned pk_hf(float lo, float hi) {
    __half2 h = __floats2half2_rn(lo, hi);
    return *(unsigned*)&h;
}
__device__ __forceinline__ float hfr(float x) {
    return __half2float(__float2half_rn(x));
}

__device__ __forceinline__ void mma16h(float (&c)[4], const uint4& a, unsigned b0, unsigned b1) {
    asm volatile("mma.sync.aligned.m16n8k16.row.col.f32.f16.f16.f32 "
                 "{%0,%1,%2,%3},{%4,%5,%6,%7},{%8,%9},{%0,%1,%2,%3};"
                 : "+f"(c[0]), "+f"(c[1]), "+f"(c[2]), "+f"(c[3])
                 : "r"(a.x), "r"(a.y), "r"(a.z), "r"(a.w), "r"(b0), "r"(b1));
}

// precombine adjacent-feature pair offsets with parametric strides
template <int MA, int MB>
__device__ __forceinline__ void precomb(int f0, int f1, int l, int& o0, int& o1) {
    int f0n = __shfl_down_sync(FULL, f0, 1);
    int f10 = __shfl_sync(FULL, f1, 0);
    f0n = (l == 31) ? f10 : f0n;
    int f1n = __shfl_down_sync(FULL, f1, 1);
    o0 = f0 * MA + f0n * MB;
    o1 = f1 * MA + f1n * MB;
}

// fp32 pair-table embed (stage C / output-facing)
template <int NF>
__device__ __forceinline__ void center_embed(int f0, int f1, int o0, int o1, int base,
                                             const char* tbB, float& c0, float& c1) {
    constexpr int SINGLE_B = ((NF + 1) / 2 - 1) * PAIR_F32_B;
    ull acc = 0;
#pragma unroll
    for (int p = 0; 2 * p + 1 < NF; p++) {
        int pa = base + 2 * p;
        int off = __shfl_sync(FULL, (pa < 32) ? o0 : o1, pa & 31);
        addp(acc, *(const ull*)(tbB + off + p * PAIR_F32_B));
    }
    int ps = base + NF - 1;
    int ia = __shfl_sync(FULL, (ps < 32) ? f0 : f1, ps & 31);
    addp(acc, *(const ull*)(tbB + (ia << 8) + SINGLE_B));
    c0 = lo32(acc); c1 = hi32(acc);
}

// fp16 pair-table embed (stages A/B centers)
template <int NF>
__device__ __forceinline__ void center_embed_h(int f0, int f1, int o0, int o1, int base,
                                               const char* tbHB, float& c0, float& c1) {
    constexpr int SINGLE_B = ((NF + 1) / 2 - 1) * PAIR_F16_B;
    __half2 acc;
    {
        int pa = base;
        int off = __shfl_sync(FULL, (pa < 32) ? o0 : o1, pa & 31);
        acc = *(const __half2*)(tbHB + off);
    }
#pragma unroll
    for (int p = 1; 2 * p + 1 < NF; p++) {
        int pa = base + 2 * p;
        int off = __shfl_sync(FULL, (pa < 32) ? o0 : o1, pa & 31);
        acc = __hadd2(acc, *(const __half2*)(tbHB + off + p * PAIR_F16_B));
    }
    int ps = base + NF - 1;
    int ia = __shfl_sync(FULL, (ps < 32) ? f0 : f1, ps & 31);
    acc = __hadd2(acc, *(const __half2*)(tbHB + (ia << 7) + SINGLE_B));
    float2 fv = __half22float2(acc);
    c0 = fv.x; c1 = fv.y;
}

// gather 8 neighbor embeds from an fp16 pair table; e kept packed, d/nn in fp32
template <int NF>
__device__ __forceinline__ void gath(const int* __restrict__ flist, const char* tbHB,
                                     float c0, float c1, int l,
                                     __half2 (&eh)[8], float (&d)[8], float (&nn)[8]) {
    constexpr int SINGLE_B = ((NF + 1) / 2 - 1) * PAIR_F16_B;
    int f0 = flist[l];
    int f1 = (l < 8 * NF - 32) ? flist[32 + l] : 0;
    int o0, o1;
    precomb<896, 128>(f0, f1, l, o0, o1);
#pragma unroll
    for (int kk = 0; kk < 8; kk++) {
        __half2 acc;
        {
            const int pa = kk * NF;
            int off = __shfl_sync(FULL, (pa < 32) ? o0 : o1, pa & 31);
            acc = *(const __half2*)(tbHB + off);
        }
#pragma unroll
        for (int p = 1; 2 * p + 1 < NF; p++) {
            const int pa = kk * NF + 2 * p;
            int off = __shfl_sync(FULL, (pa < 32) ? o0 : o1, pa & 31);
            acc = __hadd2(acc, *(const __half2*)(tbHB + off + p * PAIR_F16_B));
        }
        {
            const int ps = kk * NF + NF - 1;
            int ia = __shfl_sync(FULL, (ps < 32) ? f0 : f1, ps & 31);
            acc = __hadd2(acc, *(const __half2*)(tbHB + (ia << 7) + SINGLE_B));
        }
        eh[kk] = acc;
        float2 fv = __half22float2(acc);
        d[kk]  = fmaf(fv.y, c1, fv.x * c0);
        nn[kk] = fmaf(fv.y, fv.y, fv.x * fv.x);
    }
}

// fused fold of TWO 8-neighbor (d,nn) sets: 31 packed adds instead of 2x16,
// one rsqrt+exp per lane instead of two. Lane l owns set (l&2 ? V : U),
// neighbor j=(l>>2)&7. Returns normalized softmax weights for both sets.
__device__ __forceinline__ void dual_fold(const float (&dU)[8], const float (&nnU)[8],
                                          const float (&dV)[8], const float (&nnV)[8],
                                          float icd, int l,
                                          float (&scU)[8], float (&scV)[8]) {
    ull P[16];
#pragma unroll
    for (int k = 0; k < 8; k++) { P[k] = pack2(dU[k], nnU[k]); P[8 + k] = pack2(dV[k], nnV[k]); }
#pragma unroll
    for (int i = 0; i < 16; i++) addp(P[i], __shfl_xor_sync(FULL, P[i], 16));
    bool b4 = (l & 16) != 0;
    ull Q[8];
#pragma unroll
    for (int i = 0; i < 4; i++) { Q[i] = b4 ? P[i + 4] : P[i]; Q[4 + i] = b4 ? P[12 + i] : P[8 + i]; }
#pragma unroll
    for (int i = 0; i < 8; i++) addp(Q[i], __shfl_xor_sync(FULL, Q[i], 8));
    bool b3 = (l & 8) != 0;
    ull R[4];
    R[0] = b3 ? Q[2] : Q[0]; R[1] = b3 ? Q[3] : Q[1];
    R[2] = b3 ? Q[6] : Q[4]; R[3] = b3 ? Q[7] : Q[5];
#pragma unroll
    for (int i = 0; i < 4; i++) addp(R[i], __shfl_xor_sync(FULL, R[i], 4));
    bool b2 = (l & 4) != 0;
    ull S0 = b2 ? R[1] : R[0];
    ull S1 = b2 ? R[3] : R[2];
    addp(S0, __shfl_xor_sync(FULL, S0, 2));
    addp(S1, __shfl_xor_sync(FULL, S1, 2));
    ull T = (l & 2) ? S1 : S0;
    addp(T, __shfl_xor_sync(FULL, T, 1));
    float rr = fminf(__frsqrt_rn(hi32(T)), 1e6f);      // 1/max(sqrt(nn),1e-6)
    float mycw = __expf(lo32(T) * rr * icd);           // cosine in [-1,1]; safe
#pragma unroll
    for (int k = 0; k < 8; k++) {
        scU[k] = __shfl_sync(FULL, mycw, 4 * k);
        scV[k] = __shfl_sync(FULL, mycw, 4 * k + 2);
    }
    float sU = 0.f, sV = 0.f;
#pragma unroll
    for (int k = 0; k < 8; k++) { sU += scU[k]; sV += scV[k]; }
    float iU = __fdividef(1.f, sU), iV = __fdividef(1.f, sV);
#pragma unroll
    for (int k = 0; k < 8; k++) { scU[k] *= iU; scV[k] *= iV; }
}

// weighted relu-sum, e packed half2
__device__ __forceinline__ void wsum_h(const __half2 (&eh)[8], const float* __restrict__ wptr,
                                       const float (&sc)[8], float& o0, float& o1) {
    float4 wA = *(const float4*)wptr;
    float4 wB = *(const float4*)(wptr + 4);
    float w[8] = {wA.x, wA.y, wA.z, wA.w, wB.x, wB.y, wB.z, wB.w};
    float a0 = 0.f, a1 = 0.f;
#pragma unroll
    for (int k = 0; k < 8; k++) {
        float2 fe = __half22float2(eh[k]);
        a0 = fmaf(fmaxf(fe.x * w[k], 0.f), sc[k], a0);
        a1 = fmaf(fmaxf(fe.y * w[k], 0.f), sc[k], a1);
    }
    o0 = a0; o1 = a1;
}

// weighted relu-sum, e fp32
__device__ __forceinline__ void wsum_f(const float (&e0)[8], const float (&e1)[8],
                                       const float* __restrict__ wptr,
                                       const float (&sc)[8], float& o0, float& o1) {
    float4 wA = *(const float4*)wptr;
    float4 wB = *(const float4*)(wptr + 4);
    float w[8] = {wA.x, wA.y, wA.z, wA.w, wB.x, wB.y, wB.z, wB.w};
    float a0 = 0.f, a1 = 0.f;
#pragma unroll
    for (int k = 0; k < 8; k++) {
        a0 = fmaf(fmaxf(e0[k] * w[k], 0.f), sc[k], a0);
        a1 = fmaf(fmaxf(e1[k] * w[k], 0.f), sc[k], a1);
    }
    o0 = a0; o1 = a1;
}

// relu(W2(64x128) @ X[128x8] + b2): fp16 single-A, x hi/lo split, 2 MMAs per frag.
__device__ __forceinline__ void lin_mma(const uint4* __restrict__ AWH,
                                        float* __restrict__ xsw,
                                        const float* __restrict__ b2,
                                        int lane) {
    int g = lane >> 2, tg = lane & 3;
    float acc[4][4];
#pragma unroll
    for (int m = 0; m < 4; m++) {
        float bAv = __ldg(b2 + 16 * m + g);
        float bBv = __ldg(b2 + 16 * m + 8 + g);
        acc[m][0] = bAv; acc[m][1] = bAv;
        acc[m][2] = bBv; acc[m][3] = bBv;
    }
#pragma unroll 2
    for (int kt = 0; kt < 8; kt++) {
        int r0 = 16 * kt + 2 * tg;
        float xa0 = xsw[r0 * XS_STRIDE + g];
        float xa1 = xsw[(r0 + 1) * XS_STRIDE + g];
        float xb0 = xsw[(r0 + 8) * XS_STRIDE + g];
        float xb1 = xsw[(r0 + 9) * XS_STRIDE + g];
        unsigned Bh0 = pk_hf(xa0, xa1), Bh1 = pk_hf(xb0, xb1);
        unsigned Bl0 = pk_hf(xa0 - hfr(xa0), xa1 - hfr(xa1));
        unsigned Bl1 = pk_hf(xb0 - hfr(xb0), xb1 - hfr(xb1));
        const uint4* pa = AWH + kt * 4 * 32 + lane;
#pragma unroll
        for (int m = 0; m < 4; m++) {
            uint4 a = pa[m * 32];
            mma16h(acc[m], a, Bh0, Bh1);
            mma16h(acc[m], a, Bl0, Bl1);
        }
    }
    __syncwarp();
#pragma unroll
    for (int m = 0; m < 4; m++) {
        xsw[(16 * m + g) * XS_STRIDE + 2 * tg]         = fmaxf(acc[m][0], 0.f);
        xsw[(16 * m + g) * XS_STRIDE + 2 * tg + 1]     = fmaxf(acc[m][1], 0.f);
        xsw[(16 * m + g + 8) * XS_STRIDE + 2 * tg]     = fmaxf(acc[m][2], 0.f);
        xsw[(16 * m + g + 8) * XS_STRIDE + 2 * tg + 1] = fmaxf(acc[m][3], 0.f);
    }
    __syncwarp();
}

__global__ void __launch_bounds__(NTHREADS, 1)
gcn_kernel(const int* __restrict__ user_f, const int* __restrict__ url_f,
           const int* __restrict__ u1u_f, const float* __restrict__ u1u_w,
           const int* __restrict__ u1url_f, const float* __restrict__ u1url_w,
           const int* __restrict__ u2u_f, const float* __restrict__ u2u_w,
           const int* __restrict__ u2url_f, const float* __restrict__ u2url_w,
           const int* __restrict__ url2u_f, const float* __restrict__ url2u_w,
           const int* __restrict__ url2url_f, const float* __restrict__ url2url_w,
           const float* __restrict__ user_table, const float* __restrict__ url_table,
           const float* __restrict__ W2, const float* __restrict__ b2,
           const float* __restrict__ b1,
           const float* __restrict__ Wo, const float* __restrict__ bo,
           float* __restrict__ out, int N) {
    extern __shared__ float smf[];
    uint4* AWHv  = (uint4*)smf;
    float* upF   = smf + AW_WORDS;
    float* vpF   = upF + UP_FLOATS;
    unsigned* upH = (unsigned*)(vpF + VP_FLOATS);
    unsigned* vpH = upH + UP_ENT * 32;
    float* xsAll = (float*)(vpH + VP_ENT * 32);

    int tid = threadIdx.x;

    // ---- W2 A-fragments for m16n8k16 fp16 (frag fid = kt*4+m) ----
    for (int i = tid; i < 1024; i += NTHREADS) {
        int fid = i >> 5, ln = i & 31;
        int kt = fid >> 2, m = fid & 3;
        int gg = ln >> 2, tg = ln & 3;
        int r0 = 16 * m + gg, r1 = r0 + 8;
        int c0 = 16 * kt + 2 * tg, c1 = c0 + 1, c2 = c0 + 8, c3 = c0 + 9;
        uint4 a;
        a.x = pk_hf(W2[r0 * 128 + c0], W2[r0 * 128 + c1]);
        a.y = pk_hf(W2[r1 * 128 + c0], W2[r1 * 128 + c1]);
        a.z = pk_hf(W2[r0 * 128 + c2], W2[r0 * 128 + c3]);
        a.w = pk_hf(W2[r1 * 128 + c2], W2[r1 * 128 + c3]);
        AWHv[fid * 32 + ln] = a;
    }
    // ---- fp32 user tables ----
    for (int i = tid; i < UP_FLOATS; i += NTHREADS) {
        int e = i >> 6, q = i & 63, ln = q >> 1, c = q & 1;
        int dim = ln + 32 * c;
        float v;
        if (e < 147) {
            int p = e / 49, rem = e % 49, ia = rem / 7, ib = rem % 7;
            v = user_table[(UOFF[2 * p] + ia) * 64 + dim]
              + user_table[(UOFF[2 * p + 1] + ib) * 64 + dim];
        } else {
            v = user_table[(UOFF[6] + (e - 147)) * 64 + dim];
        }
        upF[i] = v;
    }
    // ---- fp32 url tables ----
    for (int i = tid; i < VP_FLOATS; i += NTHREADS) {
        int e = i >> 6, q = i & 63, ln = q >> 1, c = q & 1;
        int dim = ln + 32 * c;
        float v;
        if (e < 98) {
            int p = e / 49, rem = e % 49, ia = rem / 7, ib = rem % 7;
            v = url_table[(VOFF[2 * p] + ia) * 64 + dim]
              + url_table[(VOFF[2 * p + 1] + ib) * 64 + dim];
        } else {
            v = url_table[(VOFF[4] + (e - 98)) * 64 + dim];
        }
        vpF[i] = v;
    }
    __syncthreads();
    // ---- fp16 copies ----
    for (int i = tid; i < UP_ENT * 32; i += NTHREADS) {
        int e = i >> 5, ln = i & 31;
        upH[i] = pk_hf(upF[e * 64 + 2 * ln], upF[e * 64 + 2 * ln + 1]);
    }
    for (int i = tid; i < VP_ENT * 32; i += NTHREADS) {
        int e = i >> 5, ln = i & 31;
        vpH[i] = pk_hf(vpF[e * 64 + 2 * ln], vpF[e * 64 + 2 * ln + 1]);
    }
    __syncthreads();

    int l   = tid & 31;
    int wrp = tid >> 5;
    float* xsw = xsAll + wrp * XS_FLOATS;
    const char* upB  = (const char*)upF + (l << 3);
    const char* vpB  = (const char*)vpF + (l << 3);
    const char* upHB = (const char*)upH + (l << 2);
    const char* vpHB = (const char*)vpH + (l << 2);
    const uint4* AWH = AWHv;

    for (;;) {
        int n;
        if (l == 0) n = (int)atomicAdd(&g_ctr, 1u);
        n = __shfl_sync(FULL, n, 0);
        if (n >= N) break;

        // ---- stage B: user branch (hop2 -> hop1) -> eB regs ----
        float eB0[8], eB1[8];
        {
            const int* pc = u1u_f + n * 56;
            int fc0 = pc[l];
            int fc1 = (l < 24) ? pc[32 + l] : 0;
            int oc0, oc1;
            precomb<896, 128>(fc0, fc1, l, oc0, oc1);
#pragma unroll 1
            for (int k = 0; k < 8; k++) {
                float c0, c1;
                center_embed_h<7>(fc0, fc1, oc0, oc1, k * 7, upHB, c0, c1);
                float icd = fminf(__frsqrt_rn(bfly_add(fmaf(c1, c1, c0 * c0))), 1e6f);
                __half2 ehU[8], ehV[8];
                float dU[8], nnU[8], dV[8], nnV[8];
                gath<7>(u2u_f + (n * 8 + k) * 56, upHB, c0, c1, l, ehU, dU, nnU);
                gath<5>(u2url_f + (n * 8 + k) * 40, vpHB, c0, c1, l, ehV, dV, nnV);
                float scU[8], scV[8];
                dual_fold(dU, nnU, dV, nnV, icd, l, scU, scV);
                float a0, a1, q0, q1;
                wsum_h(ehU, u2u_w + (n * 8 + k) * 8, scU, a0, a1);
                wsum_h(ehV, u2url_w + (n * 8 + k) * 8, scV, q0, q1);
                xsw[l * XS_STRIDE + k]        = c0;
                xsw[(32 + l) * XS_STRIDE + k] = c1;
                xsw[(64 + l) * XS_STRIDE + k] = (a0 + q0) * 0.5f;
                xsw[(96 + l) * XS_STRIDE + k] = (a1 + q1) * 0.5f;
            }
            __syncwarp();
            lin_mma(AWH, xsw, b2, l);
#pragma unroll
            for (int k = 0; k < 8; k++) {
                eB0[k] = xsw[l * XS_STRIDE + k];
                eB1[k] = xsw[(32 + l) * XS_STRIDE + k];
            }
            __syncwarp();
        }

        // ---- stage A: url branch (hop2 -> hop1) -> Y stays in xsw ----
        {
            const int* pc = u1url_f + n * 40;
            int fc0 = pc[l];
            int fc1 = (l < 8) ? pc[32 + l] : 0;
            int oc0, oc1;
            precomb<896, 128>(fc0, fc1, l, oc0, oc1);
#pragma unroll 1
            for (int k = 0; k < 8; k++) {
                float c0, c1;
                center_embed_h<5>(fc0, fc1, oc0, oc1, k * 5, vpHB, c0, c1);
                float icd = fminf(__frsqrt_rn(bfly_add(fmaf(c1, c1, c0 * c0))), 1e6f);
                __half2 ehU[8], ehV[8];
                float dU[8], nnU[8], dV[8], nnV[8];
                gath<7>(url2u_f + (n * 8 + k) * 56, upHB, c0, c1, l, ehU, dU, nnU);
                gath<5>(url2url_f + (n * 8 + k) * 40, vpHB, c0, c1, l, ehV, dV, nnV);
                float scU[8], scV[8];
                dual_fold(dU, nnU, dV, nnV, icd, l, scU, scV);
                float a0, a1, q0, q1;
                wsum_h(ehU, url2u_w + (n * 8 + k) * 8, scU, a0, a1);
                wsum_h(ehV, url2url_w + (n * 8 + k) * 8, scV, q0, q1);
                xsw[l * XS_STRIDE + k]        = c0;
                xsw[(32 + l) * XS_STRIDE + k] = c1;
                xsw[(64 + l) * XS_STRIDE + k] = (a0 + q0) * 0.5f;
                xsw[(96 + l) * XS_STRIDE + k] = (a1 + q1) * 0.5f;
            }
            __syncwarp();
            lin_mma(AWH, xsw, b2, l);
        }

        // ---- stage C: hop1 -> center (fp32 tables: feeds output directly) ----
        {
            int uf = (l < 7) ? user_f[n * 7 + l] : 0;
            int ou0, ou1;
            precomb<1792, 256>(uf, 0, l, ou0, ou1);
            float c0, c1;
            center_embed<7>(uf, 0, ou0, ou1, 0, upB, c0, c1);
            float icd = fminf(__frsqrt_rn(bfly_add(fmaf(c1, c1, c0 * c0))), 1e6f);

            // eA from xsw (stage A's Y) — read before clobbering column 0
            float eA0[8], eA1[8];
#pragma unroll
            for (int k = 0; k < 8; k++) {
                eA0[k] = xsw[l * XS_STRIDE + k];
                eA1[k] = xsw[(32 + l) * XS_STRIDE + k];
            }

            float dA[8], nnA[8], dB[8], nnB[8];
#pragma unroll
            for (int k = 0; k < 8; k++) {
                dA[k]  = fmaf(eA1[k], c1, eA0[k] * c0);
                nnA[k] = fmaf(eA1[k], eA1[k], eA0[k] * eA0[k]);
                dB[k]  = fmaf(eB1[k], c1, eB0[k] * c0);
                nnB[k] = fmaf(eB1[k], eB1[k], eB0[k] * eB0[k]);
            }
            float scA[8], scB[8];
            dual_fold(dA, nnA, dB, nnB, icd, l, scA, scB);
            float a0, a1, q0, q1;
            wsum_f(eA0, eA1, u1url_w + n * 8, scA, a0, a1);
            wsum_f(eB0, eB1, u1u_w + n * 8, scB, q0, q1);

            xsw[l * XS_STRIDE]        = c0;
            xsw[(32 + l) * XS_STRIDE] = c1;
            xsw[(64 + l) * XS_STRIDE] = (a0 + q0) * 0.5f;
            xsw[(96 + l) * XS_STRIDE] = (a1 + q1) * 0.5f;
            __syncwarp();

            float s0 = __ldg(b1 + l), s1 = __ldg(b1 + 32 + l), u0 = 0.f, u1 = 0.f;
#pragma unroll 8
            for (int i = 0; i < 128; i += 2) {
                float x0 = xsw[i * XS_STRIDE];
                float x1 = xsw[(i + 1) * XS_STRIDE];
                float2 w0 = __half22float2(*(const __half2*)&W1TH[i * 32 + l]);
                float2 w1 = __half22float2(*(const __half2*)&W1TH[(i + 1) * 32 + l]);
                s0 = fmaf(w0.x, x0, s0); s1 = fmaf(w0.y, x0, s1);
                u0 = fmaf(w1.x, x1, u0); u1 = fmaf(w1.y, x1, u1);
            }
            __syncwarp();
            float ue0 = fmaxf(s0 + u0, 0.f);
            float ue1 = fmaxf(s1 + u1, 0.f);

            int vf = (l < 5) ? url_f[n * 5 + l] : 0;
            int ov0, ov1;
            precomb<1792, 256>(vf, 0, l, ov0, ov1);
            float v0, v1;
            center_embed<5>(vf, 0, ov0, ov1, 0, vpB, v0, v1);

            float p0 = fmaf(__ldg(Wo + l), ue0, fmaf(__ldg(Wo + 32 + l), ue1,
                       fmaf(__ldg(Wo + 64 + l), v0, __ldg(Wo + 96 + l) * v1)));
            float p1 = fmaf(__ldg(Wo + 128 + l), ue0, fmaf(__ldg(Wo + 160 + l), ue1,
                       fmaf(__ldg(Wo + 192 + l), v0, __ldg(Wo + 224 + l) * v1)));
            ull pp = pack2(p0, p1);
#pragma unroll
            for (int o = 16; o; o >>= 1) {
                ull q = __shfl_xor_sync(FULL, pp, o);
                addp(pp, q);
            }
            if (l == 0) {
                p0 = lo32(pp) + __ldg(bo); p1 = hi32(pp) + __ldg(bo + 1);
                float mm = fmaxf(p0, p1);
                float z0 = __expf(p0 - mm), z1 = __expf(p1 - mm);
                float inv = __fdividef(1.f, z0 + z1);
                *(float2*)(out + n * 2) = make_float2(z0 * inv, z1 * inv);
            }
        }
    }
}

extern "C" void kernel_launch(void* const* d_in, const int* in_sizes, int n_in,
                              void* d_out, int out_size) {
    const int*   user_f    = (const int*)d_in[1];
    const int*   url_f     = (const int*)d_in[2];
    const int*   u1u_f     = (const int*)d_in[3];
    const float* u1u_w     = (const float*)d_in[4];
    const int*   u1url_f   = (const int*)d_in[5];
    const float* u1url_w   = (const float*)d_in[6];
    const int*   u2u_f     = (const int*)d_in[7];
    const float* u2u_w     = (const float*)d_in[8];
    const int*   u2url_f   = (const int*)d_in[9];
    const float* u2url_w   = (const float*)d_in[10];
    const int*   url2u_f   = (const int*)d_in[11];
    const float* url2u_w   = (const float*)d_in[12];
    const int*   url2url_f = (const int*)d_in[13];
    const float* url2url_w = (const float*)d_in[14];
    const float* user_table = (const float*)d_in[15];
    const float* url_table  = (const float*)d_in[16];
    const float* W2 = (const float*)d_in[17];
    const float* b2 = (const float*)d_in[18];
    const float* W1 = (const float*)d_in[19];
    const float* b1 = (const float*)d_in[20];
    const float* Wo = (const float*)d_in[21];
    const float* bo = (const float*)d_in[22];
    float* out = (float*)d_out;

    int N = in_sizes[0];

    cudaFuncSetAttribute(gcn_kernel, cudaFuncAttributeMaxDynamicSharedMemorySize, SMEM_BYTES);
    int sm = 148;
    cudaDeviceGetAttribute(&sm, cudaDevAttrMultiProcessorCount, 0);

    prep_kernel<<<16, 256>>>(W1);
    gcn_kernel<<<sm, NTHREADS, SMEM_BYTES>>>(
        user_f, url_f, u1u_f, u1u_w, u1url_f, u1url_w,
        u2u_f, u2u_w, u2url_f, u2url_w,
        url2u_f, url2u_w, url2url_f, url2url_w,
        user_table, url_table, W2, b2, b1, Wo, bo, out, N);
}

// round 17
// speedup vs baseline: 1.0024x; 1.0024x over previous
#include <cuda_runtime.h>
#include <cuda_fp16.h>
#include <cstdint>

#define FULL 0xffffffffu
typedef unsigned long long ull;

__constant__ int UOFF[7] = {0, 11577, 11588, 11599, 11610, 11621, 11642};
__constant__ int VOFF[5] = {0, 4733, 4754, 4761, 4772};

constexpr int NWARP = 22;
constexpr int NTHREADS = NWARP * 32;         // 704
constexpr int XS_STRIDE = 9;
constexpr int XS_FLOATS = 128 * XS_STRIDE;   // 1152 per warp
constexpr int AW_WORDS = 32 * 32 * 4;        // 4096 words: fp16 A-frag table
constexpr int UP_FLOATS = (3 * 49 + 7) * 64; // 9856 fp32: user pair tables + single
constexpr int VP_FLOATS = (2 * 49 + 7) * 64; // 6720 fp32: url pair tables + single
constexpr int UP_ENT = 3 * 49 + 7;           // 154
constexpr int VP_ENT = 2 * 49 + 7;           // 105
constexpr int PAIR_F32_B = 49 * 256;         // fp32 pair-table stride (bytes)
constexpr int PAIR_F16_B = 49 * 128;         // fp16 pair-table stride (bytes)
constexpr int SMEM_WORDS = AW_WORDS + UP_FLOATS + VP_FLOATS
                         + UP_ENT * 32 + VP_ENT * 32 + NWARP * XS_FLOATS;
constexpr int SMEM_BYTES = SMEM_WORDS * 4;   // 217216

__device__ unsigned W1TH[128 * 32];  // half2(W1[l][i], W1[l+32][i]) at [i*32+l]
__device__ unsigned int g_ctr;

__global__ void prep_kernel(const float* __restrict__ W1) {
    int i = blockIdx.x * blockDim.x + threadIdx.x;
    if (i == 0) g_ctr = 0;
    if (i < 128 * 32) {
        int col = i >> 5, l = i & 31;
        __half2 h = __floats2half2_rn(W1[l * 128 + col], W1[(l + 32) * 128 + col]);
        W1TH[i] = *(unsigned*)&h;
    }
}

__device__ __forceinline__ float bfly_add(float v) {
#pragma unroll
    for (int o = 16; o; o >>= 1) v += __shfl_xor_sync(FULL, v, o);
    return v;
}
__device__ __forceinline__ void addp(ull& a, ull b) {
    asm("add.rn.f32x2 %0, %0, %1;" : "+l"(a) : "l"(b));
}
__device__ __forceinline__ ull pack2(float x, float y) {
    ull r; asm("mov.b64 %0, {%1, %2};" : "=l"(r) : "f"(x), "f"(y));
    return r;
}
__device__ __forceinline__ float lo32(ull v) { return __uint_as_float((unsigned)v); }
__device__ __forceinline__ float hi32(ull v) { return __uint_as_float((unsigned)(v >> 32)); }

__device__ __forceinline__ unsigned pk_hf(float lo, float hi) {
    __half2 h = __floats2half2_rn(lo, hi);
    return *(unsigned*)&h;
}
__device__ __forceinline__ float hfr(float x) {
    return __half2float(__float2half_rn(x));
}

__device__ __forceinline__ void mma16h(float (&c)[4], const uint4& a, unsigned b0, unsigned b1) {
    asm volatile("mma.sync.aligned.m16n8k16.row.col.f32.f16.f16.f32 "
                 "{%0,%1,%2,%3},{%4,%5,%6,%7},{%8,%9},{%0,%1,%2,%3};"
                 : "+f"(c[0]), "+f"(c[1]), "+f"(c[2]), "+f"(c[3])
                 : "r"(a.x), "r"(a.y), "r"(a.z), "r"(a.w), "r"(b0), "r"(b1));
}

// precombine adjacent-feature pair offsets with parametric strides:
// o0[l] = f[l]*MA + f[l+1]*MB (l+1 wraps into f1 at lane 31); o1 same for f1.
template <int MA, int MB>
__device__ __forceinline__ void precomb(int f0, int f1, int l, int& o0, int& o1) {
    int f0n = __shfl_down_sync(FULL, f0, 1);
    int f10 = __shfl_sync(FULL, f1, 0);
    f0n = (l == 31) ? f10 : f0n;
    int f1n = __shfl_down_sync(FULL, f1, 1);
    o0 = f0 * MA + f0n * MB;
    o1 = f1 * MA + f1n * MB;
}

// fp32 pair-table embed (stage C / output-facing)
template <int NF>
__device__ __forceinline__ void center_embed(int f0, int f1, int o0, int o1, int base,
                                             const char* tbB, float& c0, float& c1) {
    constexpr int SINGLE_B = ((NF + 1) / 2 - 1) * PAIR_F32_B;
    ull acc = 0;
#pragma unroll
    for (int p = 0; 2 * p + 1 < NF; p++) {
        int pa = base + 2 * p;
        int off = __shfl_sync(FULL, (pa < 32) ? o0 : o1, pa & 31);
        addp(acc, *(const ull*)(tbB + off + p * PAIR_F32_B));
    }
    int ps = base + NF - 1;
    int ia = __shfl_sync(FULL, (ps < 32) ? f0 : f1, ps & 31);
    addp(acc, *(const ull*)(tbB + (ia << 8) + SINGLE_B));
    c0 = lo32(acc); c1 = hi32(acc);
}

// fp16 pair-table embed (stages A/B: feeds cosine + x vector; noise-tolerant)
template <int NF>
__device__ __forceinline__ void center_embed_h(int f0, int f1, int o0, int o1, int base,
                                               const char* tbHB, float& c0, float& c1) {
    constexpr int SINGLE_B = ((NF + 1) / 2 - 1) * PAIR_F16_B;
    __half2 acc;
    {
        int pa = base;
        int off = __shfl_sync(FULL, (pa < 32) ? o0 : o1, pa & 31);
        acc = *(const __half2*)(tbHB + off);
    }
#pragma unroll
    for (int p = 1; 2 * p + 1 < NF; p++) {
        int pa = base + 2 * p;
        int off = __shfl_sync(FULL, (pa < 32) ? o0 : o1, pa & 31);
        acc = __hadd2(acc, *(const __half2*)(tbHB + off + p * PAIR_F16_B));
    }
    int ps = base + NF - 1;
    int ia = __shfl_sync(FULL, (ps < 32) ? f0 : f1, ps & 31);
    acc = __hadd2(acc, *(const __half2*)(tbHB + (ia << 7) + SINGLE_B));
    float2 fv = __half22float2(acc);
    c0 = fv.x; c1 = fv.y;
}

// softmax(cosine) + weighted relu-sum over 8 neighbors.
// fold-and-redistribute multi-reduce; lane 4j owns neighbor j's (d,nn) sum.
__device__ __forceinline__ void ga_tail(const float (&e0)[8], const float (&e1)[8],
                                        float (&d)[8], float (&nn)[8],
                                        const float* __restrict__ wptr, float icd,
                                        int l, float& out0, float& out1) {
    ull P[8];
#pragma unroll
    for (int kk = 0; kk < 8; kk++) P[kk] = pack2(d[kk], nn[kk]);
#pragma unroll
    for (int i = 0; i < 8; i++) addp(P[i], __shfl_xor_sync(FULL, P[i], 16));
    bool b4 = (l & 16) != 0;
    ull Q[4];
#pragma unroll
    for (int i = 0; i < 4; i++) Q[i] = b4 ? P[i + 4] : P[i];
#pragma unroll
    for (int i = 0; i < 4; i++) addp(Q[i], __shfl_xor_sync(FULL, Q[i], 8));
    bool b3 = (l & 8) != 0;
    ull R0 = b3 ? Q[2] : Q[0];
    ull R1 = b3 ? Q[3] : Q[1];
    addp(R0, __shfl_xor_sync(FULL, R0, 4));
    addp(R1, __shfl_xor_sync(FULL, R1, 4));
    ull S = (l & 4) ? R1 : R0;
    addp(S, __shfl_xor_sync(FULL, S, 2));
    addp(S, __shfl_xor_sync(FULL, S, 1));
    float rr = fminf(__frsqrt_rn(hi32(S)), 1e6f);      // 1/max(sqrt(nn),1e-6)
    float mycw = __expf(lo32(S) * rr * icd);           // cosine in [-1,1]; safe
    float4 wA = *(const float4*)wptr;
    float4 wB = *(const float4*)(wptr + 4);
    float w[8] = {wA.x, wA.y, wA.z, wA.w, wB.x, wB.y, wB.z, wB.w};
    float cw[8];
#pragma unroll
    for (int k = 0; k < 8; k++) cw[k] = __shfl_sync(FULL, mycw, 4 * k);
    float s = 0.f;
#pragma unroll
    for (int k = 0; k < 8; k++) s += cw[k];
    float inv = __fdividef(1.f, s);
    float o0 = 0.f, o1 = 0.f;
#pragma unroll
    for (int k = 0; k < 8; k++) {
        float sc = cw[k] * inv;
        o0 = fmaf(fmaxf(e0[k] * w[k], 0.f), sc, o0);
        o1 = fmaf(fmaxf(e1[k] * w[k], 0.f), sc, o1);
    }
    out0 = o0; out1 = o1;
}

// graph attention over 8 neighbors via fp16 pair tables with packed HADD2
// accumulation; single convert per neighbor.
template <int NF>
__device__ __forceinline__ void ga_tbl(const int* __restrict__ flist,
                                       const char* tbHB,
                                       const float* __restrict__ wptr,
                                       float c0, float c1, float icd, int l,
                                       float& out0, float& out1) {
    constexpr int SINGLE_B = ((NF + 1) / 2 - 1) * PAIR_F16_B;
    int f0 = flist[l];
    int f1 = (l < 8 * NF - 32) ? flist[32 + l] : 0;
    int o0, o1;
    precomb<896, 128>(f0, f1, l, o0, o1);
    float e0[8], e1[8], d[8], nn[8];
#pragma unroll
    for (int kk = 0; kk < 8; kk++) {
        __half2 acc;
        {
            const int pa = kk * NF;
            int off = __shfl_sync(FULL, (pa < 32) ? o0 : o1, pa & 31);
            acc = *(const __half2*)(tbHB + off);
        }
#pragma unroll
        for (int p = 1; 2 * p + 1 < NF; p++) {
            const int pa = kk * NF + 2 * p;
            int off = __shfl_sync(FULL, (pa < 32) ? o0 : o1, pa & 31);
            acc = __hadd2(acc, *(const __half2*)(tbHB + off + p * PAIR_F16_B));
        }
        {
            const int ps = kk * NF + NF - 1;
            int ia = __shfl_sync(FULL, (ps < 32) ? f0 : f1, ps & 31);
            acc = __hadd2(acc, *(const __half2*)(tbHB + (ia << 7) + SINGLE_B));
        }
        float2 fv = __half22float2(acc);
        float a0 = fv.x, a1 = fv.y;
        e0[kk] = a0; e1[kk] = a1;
        d[kk]  = fmaf(a1, c1, a0 * c0);
        nn[kk] = fmaf(a1, a1, a0 * a0);
    }
    ga_tail(e0, e1, d, nn, wptr, icd, l, out0, out1);
}

__device__ __forceinline__ void ga_reg(const float (&e0)[8], const float (&e1)[8],
                                       const float* __restrict__ wptr,
                                       float c0, float c1, float icd, int l,
                                       float& out0, float& out1) {
    float d[8], nn[8];
#pragma unroll
    for (int kk = 0; kk < 8; kk++) {
        d[kk]  = fmaf(e1[kk], c1, e0[kk] * c0);
        nn[kk] = fmaf(e1[kk], e1[kk], e0[kk] * e0[kk]);
    }
    ga_tail(e0, e1, d, nn, wptr, icd, l, out0, out1);
}

// relu(W2(64x128) @ X[128x8] + b2): fp16 single-A, x hi/lo split, 2 MMAs per frag.
// Y written back into xsw (stride XS_STRIDE). b2 loaded per call (L1-cached).
__device__ __forceinline__ void lin_mma(const uint4* __restrict__ AWH,
                                        float* __restrict__ xsw,
                                        const float* __restrict__ b2,
                                        int lane) {
    int g = lane >> 2, tg = lane & 3;
    float acc[4][4];
#pragma unroll
    for (int m = 0; m < 4; m++) {
        float bAv = __ldg(b2 + 16 * m + g);
        float bBv = __ldg(b2 + 16 * m + 8 + g);
        acc[m][0] = bAv; acc[m][1] = bAv;
        acc[m][2] = bBv; acc[m][3] = bBv;
    }
#pragma unroll 2
    for (int kt = 0; kt < 8; kt++) {
        int r0 = 16 * kt + 2 * tg;
        float xa0 = xsw[r0 * XS_STRIDE + g];
        float xa1 = xsw[(r0 + 1) * XS_STRIDE + g];
        float xb0 = xsw[(r0 + 8) * XS_STRIDE + g];
        float xb1 = xsw[(r0 + 9) * XS_STRIDE + g];
        unsigned Bh0 = pk_hf(xa0, xa1), Bh1 = pk_hf(xb0, xb1);
        unsigned Bl0 = pk_hf(xa0 - hfr(xa0), xa1 - hfr(xa1));
        unsigned Bl1 = pk_hf(xb0 - hfr(xb0), xb1 - hfr(xb1));
        const uint4* pa = AWH + kt * 4 * 32 + lane;
#pragma unroll
        for (int m = 0; m < 4; m++) {
            uint4 a = pa[m * 32];
            mma16h(acc[m], a, Bh0, Bh1);
            mma16h(acc[m], a, Bl0, Bl1);
        }
    }
    __syncwarp();
#pragma unroll
    for (int m = 0; m < 4; m++) {
        xsw[(16 * m + g) * XS_STRIDE + 2 * tg]         = fmaxf(acc[m][0], 0.f);
        xsw[(16 * m + g) * XS_STRIDE + 2 * tg + 1]     = fmaxf(acc[m][1], 0.f);
        xsw[(16 * m + g + 8) * XS_STRIDE + 2 * tg]     = fmaxf(acc[m][2], 0.f);
        xsw[(16 * m + g + 8) * XS_STRIDE + 2 * tg + 1] = fmaxf(acc[m][3], 0.f);
    }
    __syncwarp();
}

__global__ void __launch_bounds__(NTHREADS, 1)
gcn_kernel(const int* __restrict__ user_f, const int* __restrict__ url_f,
           const int* __restrict__ u1u_f, const float* __restrict__ u1u_w,
           const int* __restrict__ u1url_f, const float* __restrict__ u1url_w,
           const int* __restrict__ u2u_f, const float* __restrict__ u2u_w,
           const int* __restrict__ u2url_f, const float* __restrict__ u2url_w,
           const int* __restrict__ url2u_f, const float* __restrict__ url2u_w,
           const int* __restrict__ url2url_f, const float* __restrict__ url2url_w,
           const float* __restrict__ user_table, const float* __restrict__ url_table,
           const float* __restrict__ W2, const float* __restrict__ b2,
           const float* __restrict__ b1,
           const float* __restrict__ Wo, const float* __restrict__ bo,
           float* __restrict__ out, int N) {
    extern __shared__ float smf[];
    uint4* AWHv  = (uint4*)smf;
    float* upF   = smf + AW_WORDS;
    float* vpF   = upF + UP_FLOATS;
    unsigned* upH = (unsigned*)(vpF + VP_FLOATS);
    unsigned* vpH = upH + UP_ENT * 32;
    float* xsAll = (float*)(vpH + VP_ENT * 32);

    int tid = threadIdx.x;

    // ---- W2 A-fragments for m16n8k16 fp16 (frag fid = kt*4+m) ----
    for (int i = tid; i < 1024; i += NTHREADS) {
        int fid = i >> 5, ln = i & 31;
        int kt = fid >> 2, m = fid & 3;
        int gg = ln >> 2, tg = ln & 3;
        int r0 = 16 * m + gg, r1 = r0 + 8;
        int c0 = 16 * kt + 2 * tg, c1 = c0 + 1, c2 = c0 + 8, c3 = c0 + 9;
        uint4 a;
        a.x = pk_hf(W2[r0 * 128 + c0], W2[r0 * 128 + c1]);
        a.y = pk_hf(W2[r1 * 128 + c0], W2[r1 * 128 + c1]);
        a.z = pk_hf(W2[r0 * 128 + c2], W2[r0 * 128 + c3]);
        a.w = pk_hf(W2[r1 * 128 + c2], W2[r1 * 128 + c3]);
        AWHv[fid * 32 + ln] = a;
    }
    // ---- fp32 user tables: P0=(c0,c1) P1=(c2,c3) P2=(c4,c5) then 7-entry single (c6) ----
    for (int i = tid; i < UP_FLOATS; i += NTHREADS) {
        int e = i >> 6, q = i & 63, ln = q >> 1, c = q & 1;
        int dim = ln + 32 * c;
        float v;
        if (e < 147) {
            int p = e / 49, rem = e % 49, ia = rem / 7, ib = rem % 7;
            v = user_table[(UOFF[2 * p] + ia) * 64 + dim]
              + user_table[(UOFF[2 * p + 1] + ib) * 64 + dim];
        } else {
            v = user_table[(UOFF[6] + (e - 147)) * 64 + dim];
        }
        upF[i] = v;
    }
    // ---- fp32 url tables: P0=(c0,c1) P1=(c2,c3) then 7-entry single (c4) ----
    for (int i = tid; i < VP_FLOATS; i += NTHREADS) {
        int e = i >> 6, q = i & 63, ln = q >> 1, c = q & 1;
        int dim = ln + 32 * c;
        float v;
        if (e < 98) {
            int p = e / 49, rem = e % 49, ia = rem / 7, ib = rem % 7;
            v = url_table[(VOFF[2 * p] + ia) * 64 + dim]
              + url_table[(VOFF[2 * p + 1] + ib) * 64 + dim];
        } else {
            v = url_table[(VOFF[4] + (e - 98)) * 64 + dim];
        }
        vpF[i] = v;
    }
    __syncthreads();
    // ---- fp16 copies of the pair tables (derived from fp32 smem) ----
    for (int i = tid; i < UP_ENT * 32; i += NTHREADS) {
        int e = i >> 5, ln = i & 31;
        upH[i] = pk_hf(upF[e * 64 + 2 * ln], upF[e * 64 + 2 * ln + 1]);
    }
    for (int i = tid; i < VP_ENT * 32; i += NTHREADS) {
        int e = i >> 5, ln = i & 31;
        vpH[i] = pk_hf(vpF[e * 64 + 2 * ln], vpF[e * 64 + 2 * ln + 1]);
    }
    __syncthreads();

    int l   = tid & 31;
    int wrp = tid >> 5;
    float* xsw = xsAll + wrp * XS_FLOATS;
    const char* upB  = (const char*)upF + (l << 3);
    const char* vpB  = (const char*)vpF + (l << 3);
    const char* upHB = (const char*)upH + (l << 2);
    const char* vpHB = (const char*)vpH + (l << 2);
    const uint4* AWH = AWHv;

    for (;;) {
        int n;
        if (l == 0) n = (int)atomicAdd(&g_ctr, 1u);
        n = __shfl_sync(FULL, n, 0);
        if (n >= N) break;

        // ---- stage B: user branch (hop2 -> hop1) -> eB regs ----
        float eB0[8], eB1[8];
        {
            const int* pc = u1u_f + n * 56;
            int fc0 = pc[l];
            int fc1 = (l < 24) ? pc[32 + l] : 0;
            int oc0, oc1;
            precomb<896, 128>(fc0, fc1, l, oc0, oc1);
#pragma unroll 1
            for (int k = 0; k < 8; k++) {
                float c0, c1;
                center_embed_h<7>(fc0, fc1, oc0, oc1, k * 7, upHB, c0, c1);
                float icd = fminf(__frsqrt_rn(bfly_add(fmaf(c1, c1, c0 * c0))), 1e6f);
                float a0, a1, q0, q1;
                ga_tbl<7>(u2u_f + (n * 8 + k) * 56, upHB, u2u_w + (n * 8 + k) * 8,
                          c0, c1, icd, l, a0, a1);
                ga_tbl<5>(u2url_f + (n * 8 + k) * 40, vpHB, u2url_w + (n * 8 + k) * 8,
                          c0, c1, icd, l, q0, q1);
                xsw[l * XS_STRIDE + k]        = c0;
                xsw[(32 + l) * XS_STRIDE + k] = c1;
                xsw[(64 + l) * XS_STRIDE + k] = (a0 + q0) * 0.5f;
                xsw[(96 + l) * XS_STRIDE + k] = (a1 + q1) * 0.5f;
            }
            __syncwarp();
            lin_mma(AWH, xsw, b2, l);
#pragma unroll
            for (int k = 0; k < 8; k++) {
                eB0[k] = xsw[l * XS_STRIDE + k];
                eB1[k] = xsw[(32 + l) * XS_STRIDE + k];
            }
            __syncwarp();
        }

        // ---- stage A: url branch (hop2 -> hop1) -> Y stays in xsw ----
        {
            const int* pc = u1url_f + n * 40;
            int fc0 = pc[l];
            int fc1 = (l < 8) ? pc[32 + l] : 0;
            int oc0, oc1;
            precomb<896, 128>(fc0, fc1, l, oc0, oc1);
#pragma unroll 1
            for (int k = 0; k < 8; k++) {
                float c0, c1;
                center_embed_h<5>(fc0, fc1, oc0, oc1, k * 5, vpHB, c0, c1);
                float icd = fminf(__frsqrt_rn(bfly_add(fmaf(c1, c1, c0 * c0))), 1e6f);
                float a0, a1, q0, q1;
                ga_tbl<7>(url2u_f + (n * 8 + k) * 56, upHB, url2u_w + (n * 8 + k) * 8,
                          c0, c1, icd, l, a0, a1);
                ga_tbl<5>(url2url_f + (n * 8 + k) * 40, vpHB, url2url_w + (n * 8 + k) * 8,
                          c0, c1, icd, l, q0, q1);
                xsw[l * XS_STRIDE + k]        = c0;
                xsw[(32 + l) * XS_STRIDE + k] = c1;
                xsw[(64 + l) * XS_STRIDE + k] = (a0 + q0) * 0.5f;
                xsw[(96 + l) * XS_STRIDE + k] = (a1 + q1) * 0.5f;
            }
            __syncwarp();
            lin_mma(AWH, xsw, b2, l);
        }

        // ---- stage C: hop1 -> center (fp32 tables: feeds output directly) ----
        {
            int uf = (l < 7) ? user_f[n * 7 + l] : 0;
            int ou0, ou1;
            precomb<1792, 256>(uf, 0, l, ou0, ou1);
            float c0, c1;
            center_embed<7>(uf, 0, ou0, ou1, 0, upB, c0, c1);
            float icd = fminf(__frsqrt_rn(bfly_add(fmaf(c1, c1, c0 * c0))), 1e6f);

            // eA from xsw (stage A's Y) — read before clobbering column 0
            float eA0[8], eA1[8];
#pragma unroll
            for (int k = 0; k < 8; k++) {
                eA0[k] = xsw[l * XS_STRIDE + k];
                eA1[k] = xsw[(32 + l) * XS_STRIDE + k];
            }

            float a0, a1, q0, q1;
            ga_reg(eA0, eA1, u1url_w + n * 8, c0, c1, icd, l, a0, a1);
            ga_reg(eB0, eB1, u1u_w + n * 8, c0, c1, icd, l, q0, q1);

            xsw[l * XS_STRIDE]        = c0;
            xsw[(32 + l) * XS_STRIDE] = c1;
            xsw[(64 + l) * XS_STRIDE] = (a0 + q0) * 0.5f;
            xsw[(96 + l) * XS_STRIDE] = (a1 + q1) * 0.5f;
            __syncwarp();

            float s0 = __ldg(b1 + l), s1 = __ldg(b1 + 32 + l), u0 = 0.f, u1 = 0.f;
#pragma unroll 8
            for (int i = 0; i < 128; i += 2) {
                float x0 = xsw[i * XS_STRIDE];
                float x1 = xsw[(i + 1) * XS_STRIDE];
                float2 w0 = __half22float2(*(const __half2*)&W1TH[i * 32 + l]);
                float2 w1 = __half22float2(*(const __half2*)&W1TH[(i + 1) * 32 + l]);
                s0 = fmaf(w0.x, x0, s0); s1 = fmaf(w0.y, x0, s1);
                u0 = fmaf(w1.x, x1, u0); u1 = fmaf(w1.y, x1, u1);
            }
            __syncwarp();
            float ue0 = fmaxf(s0 + u0, 0.f);
            float ue1 = fmaxf(s1 + u1, 0.f);

            int vf = (l < 5) ? url_f[n * 5 + l] : 0;
            int ov0, ov1;
            precomb<1792, 256>(vf, 0, l, ov0, ov1);
            float v0, v1;
            center_embed<5>(vf, 0, ov0, ov1, 0, vpB, v0, v1);

            float p0 = fmaf(__ldg(Wo + l), ue0, fmaf(__ldg(Wo + 32 + l), ue1,
                       fmaf(__ldg(Wo + 64 + l), v0, __ldg(Wo + 96 + l) * v1)));
            float p1 = fmaf(__ldg(Wo + 128 + l), ue0, fmaf(__ldg(Wo + 160 + l), ue1,
                       fmaf(__ldg(Wo + 192 + l), v0, __ldg(Wo + 224 + l) * v1)));
            ull pp = pack2(p0, p1);
#pragma unroll
            for (int o = 16; o; o >>= 1) {
                ull q = __shfl_xor_sync(FULL, pp, o);
                addp(pp, q);
            }
            if (l == 0) {
                p0 = lo32(pp) + __ldg(bo); p1 = hi32(pp) + __ldg(bo + 1);
                float mm = fmaxf(p0, p1);
                float z0 = __expf(p0 - mm), z1 = __expf(p1 - mm);
                float inv = __fdividef(1.f, z0 + z1);
                *(float2*)(out + n * 2) = make_float2(z0 * inv, z1 * inv);
            }
        }
    }
}

extern "C" void kernel_launch(void* const* d_in, const int* in_sizes, int n_in,
                              void* d_out, int out_size) {
    const int*   user_f    = (const int*)d_in[1];
    const int*   url_f     = (const int*)d_in[2];
    const int*   u1u_f     = (const int*)d_in[3];
    const float* u1u_w     = (const float*)d_in[4];
    const int*   u1url_f   = (const int*)d_in[5];
    const float* u1url_w   = (const float*)d_in[6];
    const int*   u2u_f     = (const int*)d_in[7];
    const float* u2u_w     = (const float*)d_in[8];
    const int*   u2url_f   = (const int*)d_in[9];
    const float* u2url_w   = (const float*)d_in[10];
    const int*   url2u_f   = (const int*)d_in[11];
    const float* url2u_w   = (const float*)d_in[12];
    const int*   url2url_f = (const int*)d_in[13];
    const float* url2url_w = (const float*)d_in[14];
    const float* user_table = (const float*)d_in[15];
    const float* url_table  = (const float*)d_in[16];
    const float* W2 = (const float*)d_in[17];
    const float* b2 = (const float*)d_in[18];
    const float* W1 = (const float*)d_in[19];
    const float* b1 = (const float*)d_in[20];
    const float* Wo = (const float*)d_in[21];
    const float* bo = (const float*)d_in[22];
    float* out = (float*)d_out;

    int N = in_sizes[0];

    cudaFuncSetAttribute(gcn_kernel, cudaFuncAttributeMaxDynamicSharedMemorySize, SMEM_BYTES);
    int sm = 148;
    cudaDeviceGetAttribute(&sm, cudaDevAttrMultiProcessorCount, 0);

    prep_kernel<<<16, 256>>>(W1);
    gcn_kernel<<<sm, NTHREADS, SMEM_BYTES>>>(
        user_f, url_f, u1u_f, u1u_w, u1url_f, u1url_w,
        u2u_f, u2u_w, u2url_f, u2url_w,
        url2u_f, url2u_w, url2url_f, url2url_w,
        user_table, url_table, W2, b2, b1, Wo, bo, out, N);
}